// round 14
// baseline (speedup 1.0000x reference)
#include <cuda_runtime.h>
#include <cuda_bf16.h>
#include <math.h>
#include <stdint.h>

// Problem constants
#define BB 2
#define TT 2048
#define DM 2048
#define NH 32
#define NKV 8
#define HD 64
#define MROWS (BB*TT)          // 4096
#define QN (NH*HD)             // 2048
#define KN (NKV*HD)            // 512
#define GK DM                  // K dim of every GEMM = 2048

// Scratch (device globals — allocation-free)
__device__ float g_q[MROWS*QN];
__device__ float g_k[MROWS*KN];
__device__ float g_v[MROWS*KN];
__device__ float g_att[MROWS*QN];
__device__ float g_xc[MROWS*DM];
__device__ float g_wqc[QN*DM];
__device__ float g_wkc[KN*DM];
__device__ float g_wvc[KN*DM];
__device__ float g_woc[DM*QN];

__device__ __forceinline__ float rna(float x) {
    uint32_t u;
    asm("cvt.rna.tf32.f32 %0, %1;" : "=r"(u) : "f"(x));
    return __uint_as_float(u);
}
__device__ __forceinline__ uint32_t smem_u32(const void* p) {
    uint32_t a;
    asm("{ .reg .u64 t; cvta.to.shared.u64 t, %1; cvt.u32.u64 %0, t; }"
        : "=r"(a) : "l"(p));
    return a;
}
__device__ __forceinline__ void mma_tf32(float c[4], const uint32_t a[4],
                                         const uint32_t b[2]) {
    asm volatile(
        "mma.sync.aligned.m16n8k8.row.col.f32.tf32.tf32.f32 "
        "{%0,%1,%2,%3}, {%4,%5,%6,%7}, {%8,%9}, {%0,%1,%2,%3};"
        : "+f"(c[0]), "+f"(c[1]), "+f"(c[2]), "+f"(c[3])
        : "r"(a[0]), "r"(a[1]), "r"(a[2]), "r"(a[3]), "r"(b[0]), "r"(b[1]));
}

// ---------------------------------------------------------------------------
// Fused tf32 rounding pass, 2 independent float4s per thread (MLP=2)
// ---------------------------------------------------------------------------
#define N4_X  (MROWS*DM/4)
#define N4_WQ (QN*DM/4)
#define N4_WK (KN*DM/4)
#define N4_WV (KN*DM/4)
#define N4_WO (DM*QN/4)
#define N4_ALL (N4_X + N4_WQ + N4_WK + N4_WV + N4_WO)

__global__ void cvt_all(const float* __restrict__ x,  const float* __restrict__ wq,
                        const float* __restrict__ wk, const float* __restrict__ wv,
                        const float* __restrict__ wo,
                        float* __restrict__ xc,  float* __restrict__ wqc,
                        float* __restrict__ wkc, float* __restrict__ wvc,
                        float* __restrict__ woc) {
    int base = (blockIdx.x * blockDim.x + threadIdx.x) * 2;
#pragma unroll
    for (int e = 0; e < 2; e++) {
        int i = base + e;
        if (i >= N4_ALL) return;
        const float* src; float* dst; int off;
        if (i < N4_X)                          { src = x;  dst = xc;  off = 0; }
        else if (i < N4_X + N4_WQ)             { src = wq; dst = wqc; off = N4_X; }
        else if (i < N4_X + N4_WQ + N4_WK)     { src = wk; dst = wkc; off = N4_X + N4_WQ; }
        else if (i < N4_X + N4_WQ + N4_WK + N4_WV)
                                               { src = wv; dst = wvc; off = N4_X + N4_WQ + N4_WK; }
        else                                   { src = wo; dst = woc; off = N4_X + N4_WQ + N4_WK + N4_WV; }
        int j = i - off;
        float4 v = ((const float4*)src)[j];
        ((float4*)dst)[j] = make_float4(rna(v.x), rna(v.y), rna(v.z), rna(v.w));
    }
}

// ---------------------------------------------------------------------------
// PERSISTENT mma.sync tf32 NT GEMM: BM=128, BN=256, BK=32, 256 threads,
// 3-stage cp.async, warp tile 64x64. grid = #SMs, tile += gridDim.x.
// Epilogue per-segment mode (2 bits): 0 = raw store, 1 = rna store,
// 2 = RoPE + rna store (fused rope; warp N-tile == one 64-wide head).
// ---------------------------------------------------------------------------
#define BM 128
#define BN 256
#define BK 32
#define NCH (GK/BK)                // 64
#define RST 36
#define ATILEB (128*RST*4)         // 18432 B
#define STAGEB ((128+256)*RST*4)   // 55296 B
#define GEMM_SMEM (3*STAGEB)       // 165888 B

__global__ __launch_bounds__(256, 1) void gemm_mma(
    const float* __restrict__ A,
    const float* __restrict__ B0, const float* __restrict__ B1,
    const float* __restrict__ B2,
    float* __restrict__ C0, float* __restrict__ C1, float* __restrict__ C2,
    const float* __restrict__ cs, const float* __restrict__ sn,
    int nb1, int nb2, int ld0, int modes, int nxt, int ntiles) {
    extern __shared__ float sm[];
    const int tid = threadIdx.x;
    const int wid = tid >> 5, lane = tid & 31;
    const int g = lane >> 2, tg = lane & 3;
    const int wm = (wid >> 2) * 64;      // 0 or 64
    const int wn = (wid & 3) * 64;       // 0,64,128,192

    const uint32_t sb = smem_u32(sm);

    auto load_chunk = [&](int bm, int bn_local, const float* Bp, int kc, int s) {
        uint32_t base = sb + s * STAGEB;
#pragma unroll
        for (int j = 0; j < 12; j++) {
            int u = tid + j * 256;
            uint32_t sa;
            const float* gp;
            if (u < 1024) {
                int r = u >> 3, c16 = u & 7;
                sa = base + r * (RST*4) + c16 * 16;
                gp = A + (size_t)(bm + r) * GK + kc * BK + c16 * 4;
            } else {
                int uu = u - 1024;
                int r = uu >> 3, c16 = uu & 7;
                sa = base + ATILEB + r * (RST*4) + c16 * 16;
                gp = Bp + (size_t)(bn_local + r) * GK + kc * BK + c16 * 4;
            }
            asm volatile("cp.async.cg.shared.global [%0], [%1], 16;"
                         :: "r"(sa), "l"(gp));
        }
        asm volatile("cp.async.commit_group;" ::: "memory");
    };

    auto resolve = [&](int bn, const float*& Bp, float*& Cp, int& nb, int& ldc, int& mode) {
        int seg;
        if (bn < nb1)      { Bp = B0; Cp = C0; nb = bn;       ldc = ld0; seg = 0; }
        else if (bn < nb2) { Bp = B1; Cp = C1; nb = bn - nb1; ldc = 512; seg = 1; }
        else               { Bp = B2; Cp = C2; nb = bn - nb2; ldc = 512; seg = 2; }
        mode = (modes >> (2 * seg)) & 3;
    };

    int tile = blockIdx.x;
    if (tile >= ntiles) return;

    {
        int bm = (tile / nxt) * BM, bn = (tile % nxt) * BN;
        const float* Bp; float* Cp; int nb, ldc, mode;
        resolve(bn, Bp, Cp, nb, ldc, mode);
        load_chunk(bm, nb, Bp, 0, 0);
        load_chunk(bm, nb, Bp, 1, 1);
    }

    for (; tile < ntiles; tile += gridDim.x) {
        const int bm = (tile / nxt) * BM, bn = (tile % nxt) * BN;
        const float* Bp; float* Cp; int nb, ldc, mode;
        resolve(bn, Bp, Cp, nb, ldc, mode);

        float c[4][8][4];
#pragma unroll
        for (int i = 0; i < 4; i++)
#pragma unroll
            for (int j = 0; j < 8; j++)
#pragma unroll
                for (int q = 0; q < 4; q++) c[i][j][q] = 0.f;

        for (int t = 0; t < NCH; t++) {
            if (t + 1 < NCH) {
                asm volatile("cp.async.wait_group 1;" ::: "memory");
            } else {
                asm volatile("cp.async.wait_group 0;" ::: "memory");
            }
            __syncthreads();
            if (t + 2 < NCH)
                load_chunk(bm, nb, Bp, t + 2, (t + 2) % 3);

            const float* Ab = sm + (t % 3) * (STAGEB/4);
            const float* Bb = Ab + ATILEB/4;
#pragma unroll
            for (int ks = 0; ks < 4; ks++) {
                const int k0 = ks * 8;
                uint32_t af[4][4], bf[8][2];
#pragma unroll
                for (int tm = 0; tm < 4; tm++) {
                    const int m0 = wm + tm * 16;
                    af[tm][0] = __float_as_uint(Ab[(m0 + g)     * RST + k0 + tg]);
                    af[tm][1] = __float_as_uint(Ab[(m0 + g + 8) * RST + k0 + tg]);
                    af[tm][2] = __float_as_uint(Ab[(m0 + g)     * RST + k0 + tg + 4]);
                    af[tm][3] = __float_as_uint(Ab[(m0 + g + 8) * RST + k0 + tg + 4]);
                }
#pragma unroll
                for (int tn = 0; tn < 8; tn++) {
                    const int n0 = wn + tn * 8;
                    bf[tn][0] = __float_as_uint(Bb[(n0 + g) * RST + k0 + tg]);
                    bf[tn][1] = __float_as_uint(Bb[(n0 + g) * RST + k0 + tg + 4]);
                }
#pragma unroll
                for (int tm = 0; tm < 4; tm++)
#pragma unroll
                    for (int tn = 0; tn < 8; tn++)
                        mma_tf32(c[tm][tn], af[tm], bf[tn]);
            }
        }

        __syncthreads();

        // Prologue loads for the NEXT tile (overlap with epilogue)
        int next = tile + gridDim.x;
        if (next < ntiles) {
            int bm2 = (next / nxt) * BM, bn2 = (next % nxt) * BN;
            const float* Bp2; float* Cp2; int nb2_, ldc2, mode2;
            resolve(bn2, Bp2, Cp2, nb2_, ldc2, mode2);
            load_chunk(bm2, nb2_, Bp2, 0, 0);
            load_chunk(bm2, nb2_, Bp2, 1, 1);
        }

        // Epilogue
        if (mode == 2) {
            // RoPE + rna. Warp N-tile (64 cols) == one head. d = tn*8+2tg (<32
            // for tn<4); rotation partner at fragment tn+4.
#pragma unroll
            for (int tm = 0; tm < 4; tm++) {
                const int row0 = bm + wm + tm * 16 + g;
#pragma unroll
                for (int half = 0; half < 2; half++) {
                    const int row = row0 + half * 8;
                    const int tr = row & (TT - 1);
                    const int ci = half * 2;     // c[][ci], c[][ci+1]
#pragma unroll
                    for (int tn = 0; tn < 4; tn++) {
                        const int d = tn * 8 + 2 * tg;
                        float x1a = c[tm][tn][ci],     x1b = c[tm][tn][ci + 1];
                        float x2a = c[tm][tn + 4][ci], x2b = c[tm][tn + 4][ci + 1];
                        float c1a = cs[tr * HD + d],      c1b = cs[tr * HD + d + 1];
                        float s1a = sn[tr * HD + d],      s1b = sn[tr * HD + d + 1];
                        float c2a = cs[tr * HD + d + 32], c2b = cs[tr * HD + d + 33];
                        float s2a = sn[tr * HD + d + 32], s2b = sn[tr * HD + d + 33];
                        const int col = wn + tn * 8 + tg * 2;
                        *(float2*)&Cp[(size_t)row * ldc + nb + col] =
                            make_float2(rna(x1a * c1a - x2a * s1a),
                                        rna(x1b * c1b - x2b * s1b));
                        *(float2*)&Cp[(size_t)row * ldc + nb + col + 32] =
                            make_float2(rna(x2a * c2a + x1a * s2a),
                                        rna(x2b * c2b + x1b * s2b));
                    }
                }
            }
        } else {
            const bool rnd = (mode == 1);
#pragma unroll
            for (int tm = 0; tm < 4; tm++) {
                const int row0 = bm + wm + tm * 16 + g;
#pragma unroll
                for (int tn = 0; tn < 8; tn++) {
                    const int col = nb + wn + tn * 8 + tg * 2;
                    float2 v0 = make_float2(c[tm][tn][0], c[tm][tn][1]);
                    float2 v1 = make_float2(c[tm][tn][2], c[tm][tn][3]);
                    if (rnd) {
                        v0.x = rna(v0.x); v0.y = rna(v0.y);
                        v1.x = rna(v1.x); v1.y = rna(v1.y);
                    }
                    *(float2*)&Cp[(size_t)row0 * ldc + col]       = v0;
                    *(float2*)&Cp[(size_t)(row0 + 8) * ldc + col] = v1;
                }
            }
        }
    }
}

// ---------------------------------------------------------------------------
// Tensor-core flash attention (R8/R13-exact): 128 threads (4 warps x 32 rows),
// q-tile 128, kv-tile 64, cp.async double-buffered K/V.
// ---------------------------------------------------------------------------
#define KST 68
#define VST 72
#define PST 68
#define ATTN_SMEM ((2*64*KST + 2*64*VST + 128*PST) * 4)

__global__ __launch_bounds__(128) void attn_tc(const float* __restrict__ q,
                                               const float* __restrict__ k,
                                               const float* __restrict__ v,
                                               float* __restrict__ o) {
    const int qt = (int)gridDim.x - 1 - (int)blockIdx.x;
    const int h  = blockIdx.y;
    const int b  = blockIdx.z;
    const int kvh = h >> 2;
    const int q0 = qt * 128;

    extern __shared__ float sm[];
    float* Kb = sm;
    float* Vb = Kb + 2 * 64 * KST;
    float* Ps = Vb + 2 * 64 * VST;

    const int tid = threadIdx.x;
    const int w = tid >> 5, lane = tid & 31;
    const int g = lane >> 2, tg = lane & 3;
    const int wq0 = w * 32;

#pragma unroll
    for (int j = 0; j < 16; j++) {
        int i = tid + j * 128;
        int r = i >> 4, c4 = i & 15;
        *(float4*)&Ps[r * PST + c4 * 4] =
            *(const float4*)&q[(size_t)(b * TT + q0 + r) * QN + h * HD + c4 * 4];
    }
    __syncthreads();

    uint32_t qfl[8][4], qfh[8][4];
#pragma unroll
    for (int ks = 0; ks < 8; ks++) {
        const int k0 = ks * 8;
        qfl[ks][0] = __float_as_uint(Ps[(wq0 + g)      * PST + k0 + tg]);
        qfl[ks][1] = __float_as_uint(Ps[(wq0 + g + 8)  * PST + k0 + tg]);
        qfl[ks][2] = __float_as_uint(Ps[(wq0 + g)      * PST + k0 + tg + 4]);
        qfl[ks][3] = __float_as_uint(Ps[(wq0 + g + 8)  * PST + k0 + tg + 4]);
        qfh[ks][0] = __float_as_uint(Ps[(wq0 + g + 16) * PST + k0 + tg]);
        qfh[ks][1] = __float_as_uint(Ps[(wq0 + g + 24) * PST + k0 + tg]);
        qfh[ks][2] = __float_as_uint(Ps[(wq0 + g + 16) * PST + k0 + tg + 4]);
        qfh[ks][3] = __float_as_uint(Ps[(wq0 + g + 24) * PST + k0 + tg + 4]);
    }

    auto cp_tile = [&](int kt, int s) {
        const float* kbp = k + (size_t)(b * TT + kt * 64) * KN + kvh * HD;
        const float* vbp = v + (size_t)(b * TT + kt * 64) * KN + kvh * HD;
        float* Kd = Kb + s * 64 * KST;
        float* Vd = Vb + s * 64 * VST;
#pragma unroll
        for (int j = 0; j < 16; j++) {
            int u = tid + j * 128;
            int r = (u >> 4) & 63, c4 = u & 15;
            if (u < 1024) {
                uint32_t sa = smem_u32(&Kd[r * KST + c4 * 4]);
                asm volatile("cp.async.cg.shared.global [%0], [%1], 16;"
                             :: "r"(sa), "l"(kbp + (size_t)r * KN + c4 * 4));
            } else {
                uint32_t sa = smem_u32(&Vd[r * VST + c4 * 4]);
                asm volatile("cp.async.cg.shared.global [%0], [%1], 16;"
                             :: "r"(sa), "l"(vbp + (size_t)r * KN + c4 * 4));
            }
        }
        asm volatile("cp.async.commit_group;" ::: "memory");
    };

    float oal[8][4], oah[8][4];
#pragma unroll
    for (int nt = 0; nt < 8; nt++)
#pragma unroll
        for (int qq = 0; qq < 4; qq++) { oal[nt][qq] = 0.f; oah[nt][qq] = 0.f; }
    float mrow[4] = {-INFINITY, -INFINITY, -INFINITY, -INFINITY};
    float lrow[4] = {0.f, 0.f, 0.f, 0.f};

    const int nkt = 2 * qt + 2;
    cp_tile(0, 0);

    for (int kt = 0; kt < nkt; ++kt) {
        if (kt + 1 < nkt) {
            cp_tile(kt + 1, (kt + 1) & 1);
            asm volatile("cp.async.wait_group 1;" ::: "memory");
        } else {
            asm volatile("cp.async.wait_group 0;" ::: "memory");
        }
        __syncthreads();

        const float* Ks = Kb + (kt & 1) * 64 * KST;
        const float* Vs = Vb + (kt & 1) * 64 * VST;
        const int k0g = kt * 64;

        float scl[8][4], sch[8][4];
#pragma unroll
        for (int nt = 0; nt < 8; nt++)
#pragma unroll
            for (int qq = 0; qq < 4; qq++) { scl[nt][qq] = 0.f; sch[nt][qq] = 0.f; }

#pragma unroll
        for (int ks = 0; ks < 8; ks++) {
            const int k0 = ks * 8;
            uint32_t bf[8][2];
#pragma unroll
            for (int nt = 0; nt < 8; nt++) {
                bf[nt][0] = __float_as_uint(Ks[(nt * 8 + g) * KST + k0 + tg]);
                bf[nt][1] = __float_as_uint(Ks[(nt * 8 + g) * KST + k0 + tg + 4]);
            }
#pragma unroll
            for (int nt = 0; nt < 8; nt++) {
                mma_tf32(scl[nt], qfl[ks], bf[nt]);
                mma_tf32(sch[nt], qfh[ks], bf[nt]);
            }
        }

        const float scale = 0.125f;
        if (kt >= 2 * qt) {
            const int r0 = q0 + wq0 + g,      r1 = r0 + 8;
            const int r2 = q0 + wq0 + 16 + g, r3 = r2 + 8;
#pragma unroll
            for (int nt = 0; nt < 8; nt++) {
                int c0 = k0g + nt * 8 + 2 * tg, c1 = c0 + 1;
                scl[nt][0] = (c0 <= r0) ? scl[nt][0] * scale : -1e30f;
                scl[nt][1] = (c1 <= r0) ? scl[nt][1] * scale : -1e30f;
                scl[nt][2] = (c0 <= r1) ? scl[nt][2] * scale : -1e30f;
                scl[nt][3] = (c1 <= r1) ? scl[nt][3] * scale : -1e30f;
                sch[nt][0] = (c0 <= r2) ? sch[nt][0] * scale : -1e30f;
                sch[nt][1] = (c1 <= r2) ? sch[nt][1] * scale : -1e30f;
                sch[nt][2] = (c0 <= r3) ? sch[nt][2] * scale : -1e30f;
                sch[nt][3] = (c1 <= r3) ? sch[nt][3] * scale : -1e30f;
            }
        } else {
#pragma unroll
            for (int nt = 0; nt < 8; nt++)
#pragma unroll
                for (int qq = 0; qq < 4; qq++) {
                    scl[nt][qq] *= scale; sch[nt][qq] *= scale;
                }
        }

        float mx[4] = {-INFINITY, -INFINITY, -INFINITY, -INFINITY};
#pragma unroll
        for (int nt = 0; nt < 8; nt++) {
            mx[0] = fmaxf(mx[0], fmaxf(scl[nt][0], scl[nt][1]));
            mx[1] = fmaxf(mx[1], fmaxf(scl[nt][2], scl[nt][3]));
            mx[2] = fmaxf(mx[2], fmaxf(sch[nt][0], sch[nt][1]));
            mx[3] = fmaxf(mx[3], fmaxf(sch[nt][2], sch[nt][3]));
        }
#pragma unroll
        for (int r = 0; r < 4; r++) {
            mx[r] = fmaxf(mx[r], __shfl_xor_sync(0xffffffffu, mx[r], 1));
            mx[r] = fmaxf(mx[r], __shfl_xor_sync(0xffffffffu, mx[r], 2));
        }
        float al[4], rs[4] = {0.f, 0.f, 0.f, 0.f};
#pragma unroll
        for (int r = 0; r < 4; r++) {
            float mn = fmaxf(mrow[r], mx[r]);
            al[r] = __expf(mrow[r] - mn);
            mrow[r] = mn;
        }
#pragma unroll
        for (int nt = 0; nt < 8; nt++) {
            scl[nt][0] = __expf(scl[nt][0] - mrow[0]);
            scl[nt][1] = __expf(scl[nt][1] - mrow[0]);
            scl[nt][2] = __expf(scl[nt][2] - mrow[1]);
            scl[nt][3] = __expf(scl[nt][3] - mrow[1]);
            sch[nt][0] = __expf(sch[nt][0] - mrow[2]);
            sch[nt][1] = __expf(sch[nt][1] - mrow[2]);
            sch[nt][2] = __expf(sch[nt][2] - mrow[3]);
            sch[nt][3] = __expf(sch[nt][3] - mrow[3]);
            rs[0] += scl[nt][0] + scl[nt][1];
            rs[1] += scl[nt][2] + scl[nt][3];
            rs[2] += sch[nt][0] + sch[nt][1];
            rs[3] += sch[nt][2] + sch[nt][3];
        }
#pragma unroll
        for (int r = 0; r < 4; r++) {
            rs[r] += __shfl_xor_sync(0xffffffffu, rs[r], 1);
            rs[r] += __shfl_xor_sync(0xffffffffu, rs[r], 2);
            lrow[r] = lrow[r] * al[r] + rs[r];
        }
#pragma unroll
        for (int nt = 0; nt < 8; nt++) {
            oal[nt][0] *= al[0]; oal[nt][1] *= al[0];
            oal[nt][2] *= al[1]; oal[nt][3] *= al[1];
            oah[nt][0] *= al[2]; oah[nt][1] *= al[2];
            oah[nt][2] *= al[3]; oah[nt][3] *= al[3];
        }

#pragma unroll
        for (int nt = 0; nt < 8; nt++) {
            *(float2*)&Ps[(wq0 + g)      * PST + nt * 8 + 2 * tg] =
                make_float2(scl[nt][0], scl[nt][1]);
            *(float2*)&Ps[(wq0 + g + 8)  * PST + nt * 8 + 2 * tg] =
                make_float2(scl[nt][2], scl[nt][3]);
            *(float2*)&Ps[(wq0 + g + 16) * PST + nt * 8 + 2 * tg] =
                make_float2(sch[nt][0], sch[nt][1]);
            *(float2*)&Ps[(wq0 + g + 24) * PST + nt * 8 + 2 * tg] =
                make_float2(sch[nt][2], sch[nt][3]);
        }
        __syncwarp();

#pragma unroll
        for (int ks = 0; ks < 8; ks++) {
            const int kk = ks * 8;
            uint32_t afl[4], afh[4];
            afl[0] = __float_as_uint(Ps[(wq0 + g)      * PST + kk + tg]);
            afl[1] = __float_as_uint(Ps[(wq0 + g + 8)  * PST + kk + tg]);
            afl[2] = __float_as_uint(Ps[(wq0 + g)      * PST + kk + tg + 4]);
            afl[3] = __float_as_uint(Ps[(wq0 + g + 8)  * PST + kk + tg + 4]);
            afh[0] = __float_as_uint(Ps[(wq0 + g + 16) * PST + kk + tg]);
            afh[1] = __float_as_uint(Ps[(wq0 + g + 24) * PST + kk + tg]);
            afh[2] = __float_as_uint(Ps[(wq0 + g + 16) * PST + kk + tg + 4]);
            afh[3] = __float_as_uint(Ps[(wq0 + g + 24) * PST + kk + tg + 4]);
            uint32_t bf[8][2];
#pragma unroll
            for (int nt = 0; nt < 8; nt++) {
                bf[nt][0] = __float_as_uint(Vs[(kk + tg)     * VST + nt * 8 + g]);
                bf[nt][1] = __float_as_uint(Vs[(kk + tg + 4) * VST + nt * 8 + g]);
            }
#pragma unroll
            for (int nt = 0; nt < 8; nt++) {
                mma_tf32(oal[nt], afl, bf[nt]);
                mma_tf32(oah[nt], afh, bf[nt]);
            }
        }
        __syncthreads();
    }

    float inv[4];
#pragma unroll
    for (int r = 0; r < 4; r++) inv[r] = 1.f / lrow[r];
    const int rb = b * TT + q0 + wq0 + g;
#pragma unroll
    for (int nt = 0; nt < 8; nt++) {
        const int col = h * HD + nt * 8 + 2 * tg;
        *(float2*)&o[(size_t)rb * QN + col] =
            make_float2(rna(oal[nt][0] * inv[0]), rna(oal[nt][1] * inv[0]));
        *(float2*)&o[(size_t)(rb + 8) * QN + col] =
            make_float2(rna(oal[nt][2] * inv[1]), rna(oal[nt][3] * inv[1]));
        *(float2*)&o[(size_t)(rb + 16) * QN + col] =
            make_float2(rna(oah[nt][0] * inv[2]), rna(oah[nt][1] * inv[2]));
        *(float2*)&o[(size_t)(rb + 24) * QN + col] =
            make_float2(rna(oah[nt][2] * inv[3]), rna(oah[nt][3] * inv[3]));
    }
}

// ---------------------------------------------------------------------------
// Launcher
// ---------------------------------------------------------------------------
extern "C" void kernel_launch(void* const* d_in, const int* in_sizes, int n_in,
                              void* d_out, int out_size) {
    const float* x   = (const float*)d_in[0];
    const float* cs  = (const float*)d_in[1];
    const float* sn  = (const float*)d_in[2];
    const float* Wq  = (const float*)d_in[3];
    const float* Wk  = (const float*)d_in[4];
    const float* Wv  = (const float*)d_in[5];
    const float* Wo  = (const float*)d_in[6];
    float* out = (float*)d_out;

    float *q_ptr, *k_ptr, *v_ptr, *att_ptr;
    float *xc, *wqc, *wkc, *wvc, *woc;
    cudaGetSymbolAddress((void**)&q_ptr,  g_q);
    cudaGetSymbolAddress((void**)&k_ptr,  g_k);
    cudaGetSymbolAddress((void**)&v_ptr,  g_v);
    cudaGetSymbolAddress((void**)&att_ptr, g_att);
    cudaGetSymbolAddress((void**)&xc,   g_xc);
    cudaGetSymbolAddress((void**)&wqc,  g_wqc);
    cudaGetSymbolAddress((void**)&wkc,  g_wkc);
    cudaGetSymbolAddress((void**)&wvc,  g_wvc);
    cudaGetSymbolAddress((void**)&woc,  g_woc);

    int nsm = 148;
    cudaDeviceGetAttribute(&nsm, cudaDevAttrMultiProcessorCount, 0);

    cudaFuncSetAttribute(gemm_mma, cudaFuncAttributeMaxDynamicSharedMemorySize, GEMM_SMEM);
    cudaFuncSetAttribute(attn_tc,  cudaFuncAttributeMaxDynamicSharedMemorySize, ATTN_SMEM);

    // 1) Pre-round all GEMM operands (single launch, 2 float4/thread)
    cvt_all<<<(N4_ALL/2 + 255) / 256, 256>>>(x, Wq, Wk, Wv, Wo,
                                             xc, wqc, wkc, wvc, woc);

    // 2) Fused QKV projection (persistent, RoPE fused into epilogue):
    //    seg0 q: rope+rna (mode 2), seg1 k: rope+rna (2), seg2 v: rna (1)
    {
        int ntiles = (3072 / BN) * (MROWS / BM);
        int grid = nsm < ntiles ? nsm : ntiles;
        int modes = 2 | (2 << 2) | (1 << 4);
        gemm_mma<<<grid, 256, GEMM_SMEM>>>(
            xc, wqc, wkc, wvc, q_ptr, k_ptr, v_ptr, cs, sn,
            2048, 2560, QN, modes, 3072 / BN, ntiles);
    }

    // 3) Tensor-core flash attention
    attn_tc<<<dim3(TT / 128, NH, BB), 128, ATTN_SMEM>>>(q_ptr, k_ptr, v_ptr, att_ptr);

    // 4) Output projection (persistent, raw epilogue)
    {
        int ntiles = (DM / BN) * (MROWS / BM);
        int grid = nsm < ntiles ? nsm : ntiles;
        gemm_mma<<<grid, 256, GEMM_SMEM>>>(
            att_ptr, woc, woc, woc, out, out, out, cs, sn,
            DM, DM + 512, DM, 0, DM / BN, ntiles);
    }
}

// round 16
// speedup vs baseline: 1.0042x; 1.0042x over previous
#include <cuda_runtime.h>
#include <cuda_bf16.h>
#include <math.h>
#include <stdint.h>

// Problem constants
#define BB 2
#define TT 2048
#define DM 2048
#define NH 32
#define NKV 8
#define HD 64
#define MROWS (BB*TT)          // 4096
#define QN (NH*HD)             // 2048
#define KN (NKV*HD)            // 512
#define GK DM                  // K dim of every GEMM = 2048

// Scratch (device globals — allocation-free)
__device__ float g_q[MROWS*QN];
__device__ float g_k[MROWS*KN];
__device__ float g_v[MROWS*KN];
__device__ float g_att[MROWS*QN];
__device__ float g_xc[MROWS*DM];
__device__ float g_wqc[QN*DM];
__device__ float g_wkc[KN*DM];
__device__ float g_wvc[KN*DM];
__device__ float g_woc[DM*QN];

__device__ __forceinline__ float rna(float x) {
    uint32_t u;
    asm("cvt.rna.tf32.f32 %0, %1;" : "=r"(u) : "f"(x));
    return __uint_as_float(u);
}
__device__ __forceinline__ uint32_t smem_u32(const void* p) {
    uint32_t a;
    asm("{ .reg .u64 t; cvta.to.shared.u64 t, %1; cvt.u32.u64 %0, t; }"
        : "=r"(a) : "l"(p));
    return a;
}
__device__ __forceinline__ void mma_tf32(float c[4], const uint32_t a[4],
                                         const uint32_t b[2]) {
    asm volatile(
        "mma.sync.aligned.m16n8k8.row.col.f32.tf32.tf32.f32 "
        "{%0,%1,%2,%3}, {%4,%5,%6,%7}, {%8,%9}, {%0,%1,%2,%3};"
        : "+f"(c[0]), "+f"(c[1]), "+f"(c[2]), "+f"(c[3])
        : "r"(a[0]), "r"(a[1]), "r"(a[2]), "r"(a[3]), "r"(b[0]), "r"(b[1]));
}

// ---------------------------------------------------------------------------
// Fused tf32 rounding pass, 2 independent float4s per thread (MLP=2)
// ---------------------------------------------------------------------------
#define N4_X  (MROWS*DM/4)
#define N4_WQ (QN*DM/4)
#define N4_WK (KN*DM/4)
#define N4_WV (KN*DM/4)
#define N4_WO (DM*QN/4)
#define N4_ALL (N4_X + N4_WQ + N4_WK + N4_WV + N4_WO)

__global__ void cvt_all(const float* __restrict__ x,  const float* __restrict__ wq,
                        const float* __restrict__ wk, const float* __restrict__ wv,
                        const float* __restrict__ wo,
                        float* __restrict__ xc,  float* __restrict__ wqc,
                        float* __restrict__ wkc, float* __restrict__ wvc,
                        float* __restrict__ woc) {
    int base = (blockIdx.x * blockDim.x + threadIdx.x) * 2;
#pragma unroll
    for (int e = 0; e < 2; e++) {
        int i = base + e;
        if (i >= N4_ALL) return;
        const float* src; float* dst; int off;
        if (i < N4_X)                          { src = x;  dst = xc;  off = 0; }
        else if (i < N4_X + N4_WQ)             { src = wq; dst = wqc; off = N4_X; }
        else if (i < N4_X + N4_WQ + N4_WK)     { src = wk; dst = wkc; off = N4_X + N4_WQ; }
        else if (i < N4_X + N4_WQ + N4_WK + N4_WV)
                                               { src = wv; dst = wvc; off = N4_X + N4_WQ + N4_WK; }
        else                                   { src = wo; dst = woc; off = N4_X + N4_WQ + N4_WK + N4_WV; }
        int j = i - off;
        float4 v = ((const float4*)src)[j];
        ((float4*)dst)[j] = make_float4(rna(v.x), rna(v.y), rna(v.z), rna(v.w));
    }
}

// ---------------------------------------------------------------------------
// PERSISTENT mma.sync tf32 NT GEMM, templated on epilogue MODES so the
// O-projection instantiation carries no rope code (lower regs, no spills).
// BM=128, BN=256, BK=32, 256 threads, 3-stage cp.async, warp tile 64x64.
// mode per segment (2 bits): 0 = raw, 1 = rna, 2 = RoPE + rna.
// ---------------------------------------------------------------------------
#define BM 128
#define BN 256
#define BK 32
#define NCH (GK/BK)                // 64
#define RST 36
#define ATILEB (128*RST*4)         // 18432 B
#define STAGEB ((128+256)*RST*4)   // 55296 B
#define GEMM_SMEM (3*STAGEB)       // 165888 B

template <int MODES>
__global__ __launch_bounds__(256, 1) void gemm_mma(
    const float* __restrict__ A,
    const float* __restrict__ B0, const float* __restrict__ B1,
    const float* __restrict__ B2,
    float* __restrict__ C0, float* __restrict__ C1, float* __restrict__ C2,
    const float* __restrict__ cs, const float* __restrict__ sn,
    int nb1, int nb2, int ld0, int nxt, int ntiles) {
    extern __shared__ float sm[];
    const int tid = threadIdx.x;
    const int wid = tid >> 5, lane = tid & 31;
    const int g = lane >> 2, tg = lane & 3;
    const int wm = (wid >> 2) * 64;      // 0 or 64
    const int wn = (wid & 3) * 64;       // 0,64,128,192

    const uint32_t sb = smem_u32(sm);

    auto load_chunk = [&](int bm, int bn_local, const float* Bp, int kc, int s) {
        uint32_t base = sb + s * STAGEB;
#pragma unroll
        for (int j = 0; j < 12; j++) {
            int u = tid + j * 256;
            uint32_t sa;
            const float* gp;
            if (u < 1024) {
                int r = u >> 3, c16 = u & 7;
                sa = base + r * (RST*4) + c16 * 16;
                gp = A + (size_t)(bm + r) * GK + kc * BK + c16 * 4;
            } else {
                int uu = u - 1024;
                int r = uu >> 3, c16 = uu & 7;
                sa = base + ATILEB + r * (RST*4) + c16 * 16;
                gp = Bp + (size_t)(bn_local + r) * GK + kc * BK + c16 * 4;
            }
            asm volatile("cp.async.cg.shared.global [%0], [%1], 16;"
                         :: "r"(sa), "l"(gp));
        }
        asm volatile("cp.async.commit_group;" ::: "memory");
    };

    auto resolve = [&](int bn, const float*& Bp, float*& Cp, int& nb, int& ldc, int& mode) {
        int seg;
        if (bn < nb1)      { Bp = B0; Cp = C0; nb = bn;       ldc = ld0; seg = 0; }
        else if (bn < nb2) { Bp = B1; Cp = C1; nb = bn - nb1; ldc = 512; seg = 1; }
        else               { Bp = B2; Cp = C2; nb = bn - nb2; ldc = 512; seg = 2; }
        mode = (MODES >> (2 * seg)) & 3;
    };

    int tile = blockIdx.x;
    if (tile >= ntiles) return;

    {
        int bm = (tile / nxt) * BM, bn = (tile % nxt) * BN;
        const float* Bp; float* Cp; int nb, ldc, mode;
        resolve(bn, Bp, Cp, nb, ldc, mode);
        load_chunk(bm, nb, Bp, 0, 0);
        load_chunk(bm, nb, Bp, 1, 1);
    }

    for (; tile < ntiles; tile += gridDim.x) {
        const int bm = (tile / nxt) * BM, bn = (tile % nxt) * BN;
        const float* Bp; float* Cp; int nb, ldc, mode;
        resolve(bn, Bp, Cp, nb, ldc, mode);

        float c[4][8][4];
#pragma unroll
        for (int i = 0; i < 4; i++)
#pragma unroll
            for (int j = 0; j < 8; j++)
#pragma unroll
                for (int q = 0; q < 4; q++) c[i][j][q] = 0.f;

        for (int t = 0; t < NCH; t++) {
            if (t + 1 < NCH) {
                asm volatile("cp.async.wait_group 1;" ::: "memory");
            } else {
                asm volatile("cp.async.wait_group 0;" ::: "memory");
            }
            __syncthreads();
            if (t + 2 < NCH)
                load_chunk(bm, nb, Bp, t + 2, (t + 2) % 3);

            const float* Ab = sm + (t % 3) * (STAGEB/4);
            const float* Bb = Ab + ATILEB/4;
#pragma unroll
            for (int ks = 0; ks < 4; ks++) {
                const int k0 = ks * 8;
                uint32_t af[4][4], bf[8][2];
#pragma unroll
                for (int tm = 0; tm < 4; tm++) {
                    const int m0 = wm + tm * 16;
                    af[tm][0] = __float_as_uint(Ab[(m0 + g)     * RST + k0 + tg]);
                    af[tm][1] = __float_as_uint(Ab[(m0 + g + 8) * RST + k0 + tg]);
                    af[tm][2] = __float_as_uint(Ab[(m0 + g)     * RST + k0 + tg + 4]);
                    af[tm][3] = __float_as_uint(Ab[(m0 + g + 8) * RST + k0 + tg + 4]);
                }
#pragma unroll
                for (int tn = 0; tn < 8; tn++) {
                    const int n0 = wn + tn * 8;
                    bf[tn][0] = __float_as_uint(Bb[(n0 + g) * RST + k0 + tg]);
                    bf[tn][1] = __float_as_uint(Bb[(n0 + g) * RST + k0 + tg + 4]);
                }
#pragma unroll
                for (int tm = 0; tm < 4; tm++)
#pragma unroll
                    for (int tn = 0; tn < 8; tn++)
                        mma_tf32(c[tm][tn], af[tm], bf[tn]);
            }
        }

        __syncthreads();

        // Prologue loads for the NEXT tile (overlap with epilogue)
        int next = tile + gridDim.x;
        if (next < ntiles) {
            int bm2 = (next / nxt) * BM, bn2 = (next % nxt) * BN;
            const float* Bp2; float* Cp2; int nb2_, ldc2, mode2;
            resolve(bn2, Bp2, Cp2, nb2_, ldc2, mode2);
            load_chunk(bm2, nb2_, Bp2, 0, 0);
            load_chunk(bm2, nb2_, Bp2, 1, 1);
        }

        // Epilogue
        if (MODES != 0 && mode == 2) {
            // RoPE + rna. Warp N-tile (64 cols) == one head.
#pragma unroll
            for (int tm = 0; tm < 4; tm++) {
                const int row0 = bm + wm + tm * 16 + g;
#pragma unroll
                for (int half = 0; half < 2; half++) {
                    const int row = row0 + half * 8;
                    const int tr = row & (TT - 1);
                    const int ci = half * 2;
#pragma unroll
                    for (int tn = 0; tn < 4; tn++) {
                        const int d = tn * 8 + 2 * tg;
                        float x1a = c[tm][tn][ci],     x1b = c[tm][tn][ci + 1];
                        float x2a = c[tm][tn + 4][ci], x2b = c[tm][tn + 4][ci + 1];
                        float c1a = cs[tr * HD + d],      c1b = cs[tr * HD + d + 1];
                        float s1a = sn[tr * HD + d],      s1b = sn[tr * HD + d + 1];
                        float c2a = cs[tr * HD + d + 32], c2b = cs[tr * HD + d + 33];
                        float s2a = sn[tr * HD + d + 32], s2b = sn[tr * HD + d + 33];
                        const int col = wn + tn * 8 + tg * 2;
                        *(float2*)&Cp[(size_t)row * ldc + nb + col] =
                            make_float2(rna(x1a * c1a - x2a * s1a),
                                        rna(x1b * c1b - x2b * s1b));
                        *(float2*)&Cp[(size_t)row * ldc + nb + col + 32] =
                            make_float2(rna(x2a * c2a + x1a * s2a),
                                        rna(x2b * c2b + x1b * s2b));
                    }
                }
            }
        } else {
            const bool rnd = (mode == 1);
#pragma unroll
            for (int tm = 0; tm < 4; tm++) {
                const int row0 = bm + wm + tm * 16 + g;
#pragma unroll
                for (int tn = 0; tn < 8; tn++) {
                    const int col = nb + wn + tn * 8 + tg * 2;
                    float2 v0 = make_float2(c[tm][tn][0], c[tm][tn][1]);
                    float2 v1 = make_float2(c[tm][tn][2], c[tm][tn][3]);
                    if (MODES != 0 && rnd) {
                        v0.x = rna(v0.x); v0.y = rna(v0.y);
                        v1.x = rna(v1.x); v1.y = rna(v1.y);
                    }
                    *(float2*)&Cp[(size_t)row0 * ldc + col]       = v0;
                    *(float2*)&Cp[(size_t)(row0 + 8) * ldc + col] = v1;
                }
            }
        }
    }
}

// ---------------------------------------------------------------------------
// Tensor-core flash attention: 128 threads (4 warps x 32 q-rows),
// q-tile 128, kv-tile 64, cp.async double-buffered K/V.
// New vs R8: Q fragments pre-scaled by 0.125 (exact), warp-level skip of
// fully-masked final tile, per-warp cheap path on unmasked diagonal tile.
// ---------------------------------------------------------------------------
#define KST 68
#define VST 72
#define PST 68
#define ATTN_SMEM ((2*64*KST + 2*64*VST + 128*PST) * 4)

__global__ __launch_bounds__(128) void attn_tc(const float* __restrict__ q,
                                               const float* __restrict__ k,
                                               const float* __restrict__ v,
                                               float* __restrict__ o) {
    const int qt = (int)gridDim.x - 1 - (int)blockIdx.x;   // heavy CTAs first
    const int h  = blockIdx.y;
    const int b  = blockIdx.z;
    const int kvh = h >> 2;
    const int q0 = qt * 128;

    extern __shared__ float sm[];
    float* Kb = sm;
    float* Vb = Kb + 2 * 64 * KST;
    float* Ps = Vb + 2 * 64 * VST;

    const int tid = threadIdx.x;
    const int w = tid >> 5, lane = tid & 31;
    const int g = lane >> 2, tg = lane & 3;
    const int wq0 = w * 32;

#pragma unroll
    for (int j = 0; j < 16; j++) {
        int i = tid + j * 128;
        int r = i >> 4, c4 = i & 15;
        *(float4*)&Ps[r * PST + c4 * 4] =
            *(const float4*)&q[(size_t)(b * TT + q0 + r) * QN + h * HD + c4 * 4];
    }
    __syncthreads();

    // Q fragments pre-scaled by 1/sqrt(HD)=0.125 (exact power-of-2 on tf32)
    const float qsc = 0.125f;
    uint32_t qfl[8][4], qfh[8][4];
#pragma unroll
    for (int ks = 0; ks < 8; ks++) {
        const int k0 = ks * 8;
        qfl[ks][0] = __float_as_uint(Ps[(wq0 + g)      * PST + k0 + tg] * qsc);
        qfl[ks][1] = __float_as_uint(Ps[(wq0 + g + 8)  * PST + k0 + tg] * qsc);
        qfl[ks][2] = __float_as_uint(Ps[(wq0 + g)      * PST + k0 + tg + 4] * qsc);
        qfl[ks][3] = __float_as_uint(Ps[(wq0 + g + 8)  * PST + k0 + tg + 4] * qsc);
        qfh[ks][0] = __float_as_uint(Ps[(wq0 + g + 16) * PST + k0 + tg] * qsc);
        qfh[ks][1] = __float_as_uint(Ps[(wq0 + g + 24) * PST + k0 + tg] * qsc);
        qfh[ks][2] = __float_as_uint(Ps[(wq0 + g + 16) * PST + k0 + tg + 4] * qsc);
        qfh[ks][3] = __float_as_uint(Ps[(wq0 + g + 24) * PST + k0 + tg + 4] * qsc);
    }

    auto cp_tile = [&](int kt, int s) {
        const float* kbp = k + (size_t)(b * TT + kt * 64) * KN + kvh * HD;
        const float* vbp = v + (size_t)(b * TT + kt * 64) * KN + kvh * HD;
        float* Kd = Kb + s * 64 * KST;
        float* Vd = Vb + s * 64 * VST;
#pragma unroll
        for (int j = 0; j < 16; j++) {
            int u = tid + j * 128;
            int r = (u >> 4) & 63, c4 = u & 15;
            if (u < 1024) {
                uint32_t sa = smem_u32(&Kd[r * KST + c4 * 4]);
                asm volatile("cp.async.cg.shared.global [%0], [%1], 16;"
                             :: "r"(sa), "l"(kbp + (size_t)r * KN + c4 * 4));
            } else {
                uint32_t sa = smem_u32(&Vd[r * VST + c4 * 4]);
                asm volatile("cp.async.cg.shared.global [%0], [%1], 16;"
                             :: "r"(sa), "l"(vbp + (size_t)r * KN + c4 * 4));
            }
        }
        asm volatile("cp.async.commit_group;" ::: "memory");
    };

    float oal[8][4], oah[8][4];
#pragma unroll
    for (int nt = 0; nt < 8; nt++)
#pragma unroll
        for (int qq = 0; qq < 4; qq++) { oal[nt][qq] = 0.f; oah[nt][qq] = 0.f; }
    float mrow[4] = {-INFINITY, -INFINITY, -INFINITY, -INFINITY};
    float lrow[4] = {0.f, 0.f, 0.f, 0.f};

    const int nkt = 2 * qt + 2;
    cp_tile(0, 0);

    for (int kt = 0; kt < nkt; ++kt) {
        if (kt + 1 < nkt) {
            cp_tile(kt + 1, (kt + 1) & 1);
            asm volatile("cp.async.wait_group 1;" ::: "memory");
        } else {
            asm volatile("cp.async.wait_group 0;" ::: "memory");
        }
        __syncthreads();

        const int k0g = kt * 64;
        // Warp-level skip: tile fully masked for this warp (contributions are
        // exact zeros with alpha=1) -> skip compute, keep barriers.
        if (k0g <= q0 + wq0 + 31) {
            const float* Ks = Kb + (kt & 1) * 64 * KST;
            const float* Vs = Vb + (kt & 1) * 64 * VST;

            float scl[8][4], sch[8][4];
#pragma unroll
            for (int nt = 0; nt < 8; nt++)
#pragma unroll
                for (int qq = 0; qq < 4; qq++) { scl[nt][qq] = 0.f; sch[nt][qq] = 0.f; }

#pragma unroll
            for (int ks = 0; ks < 8; ks++) {
                const int k0 = ks * 8;
                uint32_t bf[8][2];
#pragma unroll
                for (int nt = 0; nt < 8; nt++) {
                    bf[nt][0] = __float_as_uint(Ks[(nt * 8 + g) * KST + k0 + tg]);
                    bf[nt][1] = __float_as_uint(Ks[(nt * 8 + g) * KST + k0 + tg + 4]);
                }
#pragma unroll
                for (int nt = 0; nt < 8; nt++) {
                    mma_tf32(scl[nt], qfl[ks], bf[nt]);
                    mma_tf32(sch[nt], qfh[ks], bf[nt]);
                }
            }

            // Mask only if this warp's rows intersect the diagonal of this tile
            if (k0g + 63 > q0 + wq0) {
                const int r0 = q0 + wq0 + g,      r1 = r0 + 8;
                const int r2 = q0 + wq0 + 16 + g, r3 = r2 + 8;
#pragma unroll
                for (int nt = 0; nt < 8; nt++) {
                    int c0 = k0g + nt * 8 + 2 * tg, c1 = c0 + 1;
                    scl[nt][0] = (c0 <= r0) ? scl[nt][0] : -1e30f;
                    scl[nt][1] = (c1 <= r0) ? scl[nt][1] : -1e30f;
                    scl[nt][2] = (c0 <= r1) ? scl[nt][2] : -1e30f;
                    scl[nt][3] = (c1 <= r1) ? scl[nt][3] : -1e30f;
                    sch[nt][0] = (c0 <= r2) ? sch[nt][0] : -1e30f;
                    sch[nt][1] = (c1 <= r2) ? sch[nt][1] : -1e30f;
                    sch[nt][2] = (c0 <= r3) ? sch[nt][2] : -1e30f;
                    sch[nt][3] = (c1 <= r3) ? sch[nt][3] : -1e30f;
                }
            }

            // ---- online softmax ----
            float mx[4] = {-INFINITY, -INFINITY, -INFINITY, -INFINITY};
#pragma unroll
            for (int nt = 0; nt < 8; nt++) {
                mx[0] = fmaxf(mx[0], fmaxf(scl[nt][0], scl[nt][1]));
                mx[1] = fmaxf(mx[1], fmaxf(scl[nt][2], scl[nt][3]));
                mx[2] = fmaxf(mx[2], fmaxf(sch[nt][0], sch[nt][1]));
                mx[3] = fmaxf(mx[3], fmaxf(sch[nt][2], sch[nt][3]));
            }
#pragma unroll
            for (int r = 0; r < 4; r++) {
                mx[r] = fmaxf(mx[r], __shfl_xor_sync(0xffffffffu, mx[r], 1));
                mx[r] = fmaxf(mx[r], __shfl_xor_sync(0xffffffffu, mx[r], 2));
            }
            float al[4], rs[4] = {0.f, 0.f, 0.f, 0.f};
#pragma unroll
            for (int r = 0; r < 4; r++) {
                float mn = fmaxf(mrow[r], mx[r]);
                al[r] = __expf(mrow[r] - mn);
                mrow[r] = mn;
            }
#pragma unroll
            for (int nt = 0; nt < 8; nt++) {
                scl[nt][0] = __expf(scl[nt][0] - mrow[0]);
                scl[nt][1] = __expf(scl[nt][1] - mrow[0]);
                scl[nt][2] = __expf(scl[nt][2] - mrow[1]);
                scl[nt][3] = __expf(scl[nt][3] - mrow[1]);
                sch[nt][0] = __expf(sch[nt][0] - mrow[2]);
                sch[nt][1] = __expf(sch[nt][1] - mrow[2]);
                sch[nt][2] = __expf(sch[nt][2] - mrow[3]);
                sch[nt][3] = __expf(sch[nt][3] - mrow[3]);
                rs[0] += scl[nt][0] + scl[nt][1];
                rs[1] += scl[nt][2] + scl[nt][3];
                rs[2] += sch[nt][0] + sch[nt][1];
                rs[3] += sch[nt][2] + sch[nt][3];
            }
#pragma unroll
            for (int r = 0; r < 4; r++) {
                rs[r] += __shfl_xor_sync(0xffffffffu, rs[r], 1);
                rs[r] += __shfl_xor_sync(0xffffffffu, rs[r], 2);
                lrow[r] = lrow[r] * al[r] + rs[r];
            }
#pragma unroll
            for (int nt = 0; nt < 8; nt++) {
                oal[nt][0] *= al[0]; oal[nt][1] *= al[0];
                oal[nt][2] *= al[1]; oal[nt][3] *= al[1];
                oah[nt][0] *= al[2]; oah[nt][1] *= al[2];
                oah[nt][2] *= al[3]; oah[nt][3] *= al[3];
            }

            // ---- P to smem (warp-private rows), reload as A-frags ----
#pragma unroll
            for (int nt = 0; nt < 8; nt++) {
                *(float2*)&Ps[(wq0 + g)      * PST + nt * 8 + 2 * tg] =
                    make_float2(scl[nt][0], scl[nt][1]);
                *(float2*)&Ps[(wq0 + g + 8)  * PST + nt * 8 + 2 * tg] =
                    make_float2(scl[nt][2], scl[nt][3]);
                *(float2*)&Ps[(wq0 + g + 16) * PST + nt * 8 + 2 * tg] =
                    make_float2(sch[nt][0], sch[nt][1]);
                *(float2*)&Ps[(wq0 + g + 24) * PST + nt * 8 + 2 * tg] =
                    make_float2(sch[nt][2], sch[nt][3]);
            }
            __syncwarp();

            // ---- O += P @ V ----
#pragma unroll
            for (int ks = 0; ks < 8; ks++) {
                const int kk = ks * 8;
                uint32_t afl[4], afh[4];
                afl[0] = __float_as_uint(Ps[(wq0 + g)      * PST + kk + tg]);
                afl[1] = __float_as_uint(Ps[(wq0 + g + 8)  * PST + kk + tg]);
                afl[2] = __float_as_uint(Ps[(wq0 + g)      * PST + kk + tg + 4]);
                afl[3] = __float_as_uint(Ps[(wq0 + g + 8)  * PST + kk + tg + 4]);
                afh[0] = __float_as_uint(Ps[(wq0 + g + 16) * PST + kk + tg]);
                afh[1] = __float_as_uint(Ps[(wq0 + g + 24) * PST + kk + tg]);
                afh[2] = __float_as_uint(Ps[(wq0 + g + 16) * PST + kk + tg + 4]);
                afh[3] = __float_as_uint(Ps[(wq0 + g + 24) * PST + kk + tg + 4]);
                uint32_t bf[8][2];
#pragma unroll
                for (int nt = 0; nt < 8; nt++) {
                    bf[nt][0] = __float_as_uint(Vs[(kk + tg)     * VST + nt * 8 + g]);
                    bf[nt][1] = __float_as_uint(Vs[(kk + tg + 4) * VST + nt * 8 + g]);
                }
#pragma unroll
                for (int nt = 0; nt < 8; nt++) {
                    mma_tf32(oal[nt], afl, bf[nt]);
                    mma_tf32(oah[nt], afh, bf[nt]);
                }
            }
        }
        __syncthreads();   // all warps done with this K/V buffer
    }

    float inv[4];
#pragma unroll
    for (int r = 0; r < 4; r++) inv[r] = 1.f / lrow[r];
    const int rb = b * TT + q0 + wq0 + g;
#pragma unroll
    for (int nt = 0; nt < 8; nt++) {
        const int col = h * HD + nt * 8 + 2 * tg;
        *(float2*)&o[(size_t)rb * QN + col] =
            make_float2(rna(oal[nt][0] * inv[0]), rna(oal[nt][1] * inv[0]));
        *(float2*)&o[(size_t)(rb + 8) * QN + col] =
            make_float2(rna(oal[nt][2] * inv[1]), rna(oal[nt][3] * inv[1]));
        *(float2*)&o[(size_t)(rb + 16) * QN + col] =
            make_float2(rna(oah[nt][0] * inv[2]), rna(oah[nt][1] * inv[2]));
        *(float2*)&o[(size_t)(rb + 24) * QN + col] =
            make_float2(rna(oah[nt][2] * inv[3]), rna(oah[nt][3] * inv[3]));
    }
}

// ---------------------------------------------------------------------------
// Launcher
// ---------------------------------------------------------------------------
#define MODES_QKV (2 | (2 << 2) | (1 << 4))

extern "C" void kernel_launch(void* const* d_in, const int* in_sizes, int n_in,
                              void* d_out, int out_size) {
    const float* x   = (const float*)d_in[0];
    const float* cs  = (const float*)d_in[1];
    const float* sn  = (const float*)d_in[2];
    const float* Wq  = (const float*)d_in[3];
    const float* Wk  = (const float*)d_in[4];
    const float* Wv  = (const float*)d_in[5];
    const float* Wo  = (const float*)d_in[6];
    float* out = (float*)d_out;

    float *q_ptr, *k_ptr, *v_ptr, *att_ptr;
    float *xc, *wqc, *wkc, *wvc, *woc;
    cudaGetSymbolAddress((void**)&q_ptr,  g_q);
    cudaGetSymbolAddress((void**)&k_ptr,  g_k);
    cudaGetSymbolAddress((void**)&v_ptr,  g_v);
    cudaGetSymbolAddress((void**)&att_ptr, g_att);
    cudaGetSymbolAddress((void**)&xc,   g_xc);
    cudaGetSymbolAddress((void**)&wqc,  g_wqc);
    cudaGetSymbolAddress((void**)&wkc,  g_wkc);
    cudaGetSymbolAddress((void**)&wvc,  g_wvc);
    cudaGetSymbolAddress((void**)&woc,  g_woc);

    int nsm = 148;
    cudaDeviceGetAttribute(&nsm, cudaDevAttrMultiProcessorCount, 0);

    cudaFuncSetAttribute(gemm_mma<MODES_QKV>, cudaFuncAttributeMaxDynamicSharedMemorySize, GEMM_SMEM);
    cudaFuncSetAttribute(gemm_mma<0>,         cudaFuncAttributeMaxDynamicSharedMemorySize, GEMM_SMEM);
    cudaFuncSetAttribute(attn_tc, cudaFuncAttributeMaxDynamicSharedMemorySize, ATTN_SMEM);

    // 1) Pre-round all GEMM operands
    cvt_all<<<(N4_ALL/2 + 255) / 256, 256>>>(x, Wq, Wk, Wv, Wo,
                                             xc, wqc, wkc, wvc, woc);

    // 2) Fused QKV projection (persistent, RoPE fused into epilogue)
    {
        int ntiles = (3072 / BN) * (MROWS / BM);
        int grid = nsm < ntiles ? nsm : ntiles;
        gemm_mma<MODES_QKV><<<grid, 256, GEMM_SMEM>>>(
            xc, wqc, wkc, wvc, q_ptr, k_ptr, v_ptr, cs, sn,
            2048, 2560, QN, 3072 / BN, ntiles);
    }

    // 3) Tensor-core flash attention
    attn_tc<<<dim3(TT / 128, NH, BB), 128, ATTN_SMEM>>>(q_ptr, k_ptr, v_ptr, att_ptr);

    // 4) Output projection (persistent, lean instantiation — no rope code)
    {
        int ntiles = (DM / BN) * (MROWS / BM);
        int grid = nsm < ntiles ? nsm : ntiles;
        gemm_mma<0><<<grid, 256, GEMM_SMEM>>>(
            att_ptr, woc, woc, woc, out, out, out, cs, sn,
            DM, DM + 512, DM, DM / BN, ntiles);
    }
}